// round 16
// baseline (speedup 1.0000x reference)
#include <cuda_runtime.h>
#include <math.h>

#define PB 8
#define PC 64
#define PH 256
#define PW 256
#define PKX 64
#define PKY 32
#define NROWS (PB*PC*PH)

typedef unsigned long long u64;

// ---- scratch (device globals; no runtime allocation) ----
__device__ __align__(16) float  g_T[256*64];
__device__ __align__(16) float  g_cos[256];
__device__ __align__(16) float  g_sin[256];
__device__ __align__(16) float2 g_ct[256];            // (cos, sin) pairs
__device__ __align__(16) float2 g_E[128*64];          // fwdH twiddles E[h][kxp]
__device__ __align__(16) float2 g_X1[PB*PC*PH*PKY];   // after fwd-W  [b,c,h,ky]
__device__ __align__(16) float2 g_XF[PB*PC*PKX*PKY];  // after fwd-H  [b,c,kx',ky]
__device__ __align__(16) float2 g_OF[PB*PC*PKX*PKY];  // after mix
__device__ __align__(16) float2 g_Y1[PB*PC*PKY*PH];   // after inv-H  [b,c,ky,h]
__device__ __align__(16) float  g_y[PB*PC*PH*PW];     // spectral conv out
__device__ __align__(16) float  g_z[PB*PC*PH*PW];     // MLP out
__device__ __align__(16) float  g_p1[PB*PC*4*2];
__device__ __align__(16) float  g_p2[PB*PH*2];
__device__ __align__(16) float  g_s1[PB*2];
__device__ __align__(16) float  g_s2[PB*2];
__device__ __align__(16) float  g_gb[PB*PC*2];

__device__ __forceinline__ float gelu_f(float v) {
    return 0.5f * v * (1.0f + erff(v * 0.7071067811865476f));
}

// ---- packed f32x2 helpers (bit-identical fp32 FMA, 2 per issue slot) ----
__device__ __forceinline__ u64 fma2(u64 a, u64 b, u64 c) {
    u64 d;
    asm("fma.rn.f32x2 %0, %1, %2, %3;" : "=l"(d) : "l"(a), "l"(b), "l"(c));
    return d;
}
__device__ __forceinline__ u64 pack2(float v) {
    u64 d;
    asm("mov.b64 %0, {%1, %1};" : "=l"(d) : "f"(v));
    return d;
}
__device__ __forceinline__ u64 packab(float a, float b) {
    u64 d;
    asm("mov.b64 %0, {%1, %2};" : "=l"(d) : "f"(a), "f"(b));
    return d;
}
__device__ __forceinline__ void upk2(u64 v, float& lo, float& hi) {
    asm("mov.b64 {%0, %1}, %2;" : "=f"(lo), "=f"(hi) : "l"(v));
}

// ---- twiddle tables: fully parallel grid-stride ----
__global__ void k_tab() {
    int i = blockIdx.x * blockDim.x + threadIdx.x;
    if (i < 8192) {
        int j = i >> 5, ky = i & 31;
        int idx = (ky * j) & 255;
        double s2, c2;
        sincospi((double)idx * (2.0 / 256.0), &s2, &c2);
        g_T[j * 64 + 2 * ky]     = (float)c2;
        g_T[j * 64 + 2 * ky + 1] = (float)(-s2);
    } else if (i < 8448) {
        int j = i - 8192;
        double sd, cd;
        sincospi((double)j * (2.0 / 256.0), &sd, &cd);
        g_cos[j] = (float)cd;
        g_sin[j] = (float)sd;
        g_ct[j] = make_float2((float)cd, (float)sd);
    } else if (i < 16640) {
        int k = i - 8448;
        int h = k >> 6, kxp = k & 63;
        int kxm = kxp + ((kxp >= 32) ? 192 : 0);
        int idx = (kxm * h) & 255;
        double s2, c2;
        sincospi((double)idx * (2.0 / 256.0), &s2, &c2);
        g_E[k] = make_float2((float)c2, (float)s2);
    }
}

// ---- FiLM gamma/beta ----
__global__ void k_film(const float* __restrict__ t,
                       const float* __restrict__ gw, const float* __restrict__ gb,
                       const float* __restrict__ bw, const float* __restrict__ bb) {
    int b = blockIdx.x, o = threadIdx.x;
    float g = gb[o], be = bb[o];
    for (int c = 0; c < PC; ++c) {
        float tv = t[b * PC + c];
        g  += gw[o * PC + c] * tv;
        be += bw[o * PC + c] * tv;
    }
    g_gb[(b * PC + o) * 2]     = g;
    g_gb[(b * PC + o) * 2 + 1] = be;
}

// ---- forward DFT along W, radix-2; T via LDG, packed FFMA2 ----
__global__ void __launch_bounds__(256) k_fwdW(const float* __restrict__ x) {
    extern __shared__ char smraw[];
    float2* su = (float2*)smraw;            // [row 64][w<128] (u0,u1)  64KB
    int tid = threadIdx.x;
    size_t base = (size_t)blockIdx.x * 64 * 256;

    for (int i = tid; i < 2048; i += 256) {
        int row = i >> 5, w4 = (i & 31) * 4;
        float4 a = *(const float4*)&x[base + row * 256 + w4];
        float4 b = *(const float4*)&x[base + row * 256 + w4 + 128];
        float4* d = (float4*)&su[row * 128 + w4];
        d[0] = make_float4(a.x + b.x, a.x - b.x, a.y + b.y, a.y - b.y);
        d[1] = make_float4(a.z + b.z, a.z - b.z, a.w + b.w, a.w - b.w);
    }
    __syncthreads();

    int r0 = (tid >> 3) * 2;
    int c0 = (tid & 7) * 8;

    u64 acc[2][4];
#pragma unroll
    for (int r = 0; r < 2; ++r)
#pragma unroll
        for (int p = 0; p < 4; ++p) acc[r][p] = 0ull;

    const float2* rowA = su + r0 * 128;
    const float2* rowB = rowA + 128;
#pragma unroll 4
    for (int k = 0; k < 128; ++k) {
        float2 ua = rowA[k];
        float2 ub = rowB[k];
        ulonglong2 t01 = *(const ulonglong2*)&g_T[k * 64 + c0];
        ulonglong2 t23 = *(const ulonglong2*)&g_T[k * 64 + c0 + 4];
        u64 uax = pack2(ua.x), uay = pack2(ua.y);
        u64 ubx = pack2(ub.x), uby = pack2(ub.y);
        acc[0][0] = fma2(uax, t01.x, acc[0][0]);
        acc[0][1] = fma2(uay, t01.y, acc[0][1]);
        acc[0][2] = fma2(uax, t23.x, acc[0][2]);
        acc[0][3] = fma2(uay, t23.y, acc[0][3]);
        acc[1][0] = fma2(ubx, t01.x, acc[1][0]);
        acc[1][1] = fma2(uby, t01.y, acc[1][1]);
        acc[1][2] = fma2(ubx, t23.x, acc[1][2]);
        acc[1][3] = fma2(uby, t23.y, acc[1][3]);
    }
    float* go = (float*)g_X1 + (size_t)blockIdx.x * 64 * 64;
#pragma unroll
    for (int r = 0; r < 2; ++r) {
        float o[8];
#pragma unroll
        for (int p = 0; p < 4; ++p) upk2(acc[r][p], o[2 * p], o[2 * p + 1]);
        *(float4*)&go[(r0 + r) * 64 + c0]     = make_float4(o[0], o[1], o[2], o[3]);
        *(float4*)&go[(r0 + r) * 64 + c0 + 4] = make_float4(o[4], o[5], o[6], o[7]);
    }
}

// ---- forward DFT along H, radix-2; ky-split + E via LDG + packed FFMA2 ----
__global__ void __launch_bounds__(256) k_fwdH() {
    extern __shared__ char smraw[];
    float2* sv0 = (float2*)smraw;                    // [h<128][16] sum operand
    float2* sv1 = (float2*)(smraw + 16384 + 32);     // diff operand (skewed)
    int tid = threadIdx.x;
    int bc = blockIdx.x >> 1, kh = blockIdx.x & 1;

    const float4* src = (const float4*)(g_X1 + (size_t)bc * 8192);
    float4* d0 = (float4*)sv0;
    float4* d1 = (float4*)sv1;
    for (int i = tid; i < 1024; i += 256) {
        int h = i >> 3, j = i & 7;
        int s = h * 16 + kh * 8 + j;
        float4 a = src[s];
        float4 b = src[s + 2048];                    // h+128
        d0[i] = make_float4(a.x + b.x, a.y + b.y, a.z + b.z, a.w + b.w);
        d1[i] = make_float4(a.x - b.x, a.y - b.y, a.z - b.z, a.w - b.w);
    }
    __syncthreads();

    int kxp = tid & 63;
    int ky0 = (tid >> 6) * 4;
    const float2* sv = (kxp & 1) ? sv1 : sv0;
    const float2* E = g_E + kxp;

    u64 P[4], Q[4];
#pragma unroll
    for (int j = 0; j < 4; ++j) { P[j] = 0ull; Q[j] = 0ull; }

#pragma unroll 4
    for (int h = 0; h < 128; ++h) {
        float2 e = E[h * 64];
        u64 ex = pack2(e.x), ey = pack2(e.y);
        const float2* row = &sv[h * 16 + ky0];
        ulonglong2 vA = *(const ulonglong2*)&row[0];
        ulonglong2 vB = *(const ulonglong2*)&row[2];
        P[0] = fma2(vA.x, ex, P[0]);  Q[0] = fma2(vA.x, ey, Q[0]);
        P[1] = fma2(vA.y, ex, P[1]);  Q[1] = fma2(vA.y, ey, Q[1]);
        P[2] = fma2(vB.x, ex, P[2]);  Q[2] = fma2(vB.x, ey, Q[2]);
        P[3] = fma2(vB.y, ex, P[3]);  Q[3] = fma2(vB.y, ey, Q[3]);
    }
    float2 acc[4];
#pragma unroll
    for (int j = 0; j < 4; ++j) {
        float px, py, qx, qy;
        upk2(P[j], px, py);
        upk2(Q[j], qx, qy);
        acc[j] = make_float2(px + qy, py - qx);
    }
    int kyg = kh * 16 + ky0;
    float2* o = g_XF + ((size_t)bc * 64 + kxp) * 32 + kyg;
    *(float4*)&o[0] = make_float4(acc[0].x, acc[0].y, acc[1].x, acc[1].y);
    *(float4*)&o[2] = make_float4(acc[2].x, acc[2].y, acc[3].x, acc[3].y);
}

// ---- per-mode complex channel mixing, packed FFMA2 P/Q ----
__global__ void __launch_bounds__(512)
k_mix(const float* __restrict__ w1r, const float* __restrict__ w1i,
      const float* __restrict__ w2r, const float* __restrict__ w2i) {
    extern __shared__ char smraw[];
    float2* sXF = (float2*)smraw;   // [(b*64+i)*16 + kyl], 8192 float2 = 64KB
    int kxp   = blockIdx.x >> 2;
    int ohalf = (blockIdx.x >> 1) & 1;
    int kh    = blockIdx.x & 1;
    int tid = threadIdx.x;

    for (int i = tid; i < 8192; i += 512) {
        int b = i >> 10, rest = i & 1023, ii = rest >> 4, kk = rest & 15;
        sXF[i] = g_XF[(((size_t)b * PC + ii) * PKX + kxp) * PKY + kh * 16 + kk];
    }
    __syncthreads();

    int o   = ohalf * 32 + (tid >> 4);
    int kyl = tid & 15;
    int ky  = kh * 16 + kyl;
    const float* wr; const float* wi; int kxl;
    if (kxp < 32) { wr = w1r; wi = w1i; kxl = kxp; }
    else          { wr = w2r; wi = w2i; kxl = kxp - 32; }

    u64 P[8], Q[8];
#pragma unroll
    for (int b = 0; b < 8; ++b) { P[b] = 0ull; Q[b] = 0ull; }

    const float* wrp = wr + (size_t)o * 1024 + kxl * 32 + ky;
    const float* wip = wi + (size_t)o * 1024 + kxl * 32 + ky;
#pragma unroll 2
    for (int i = 0; i < 64; ++i) {
        u64 wr2 = pack2(wrp[(size_t)i * 65536]);
        u64 wi2 = pack2(wip[(size_t)i * 65536]);
        const u64* vp = (const u64*)&sXF[i * 16 + kyl];
#pragma unroll
        for (int b = 0; b < 8; ++b) {
            u64 v = vp[b * 1024];
            P[b] = fma2(v, wr2, P[b]);
            Q[b] = fma2(v, wi2, Q[b]);
        }
    }
#pragma unroll
    for (int b = 0; b < 8; ++b) {
        float px, py, qx, qy;
        upk2(P[b], px, py);
        upk2(Q[b], qx, qy);
        g_OF[(((size_t)b * PC + o) * PKX + kxp) * PKY + ky] =
            make_float2(px - qy, py + qx);
    }
}

// ---- inverse DFT along H, radix-2; h-pair packed FFMA2 (bit-identical) ----
__global__ void __launch_bounds__(256) k_invH() {
    __shared__ float2 sOF[2048];
    __shared__ float2 ct[256];
    int tid = threadIdx.x, bc = blockIdx.x;

    const float4* src = (const float4*)(g_OF + (size_t)bc * 2048);
    float4* dst = (float4*)sOF;
    for (int i = tid; i < 1024; i += 256) dst[i] = src[i];
    ct[tid] = g_ct[tid];
    __syncthreads();

    int h0  = (tid >> 3) * 4;     // 4 h = 2 packed pairs
    int ky0 = (tid & 7) * 4;

    u64 Re[2][2][4], Im[2][2][4];
#pragma unroll
    for (int q = 0; q < 2; ++q)
#pragma unroll
        for (int p = 0; p < 2; ++p)
#pragma unroll
            for (int j = 0; j < 4; ++j) { Re[q][p][j] = 0ull; Im[q][p][j] = 0ull; }

    for (int kxp = 0; kxp < 64; kxp += 2) {
        int kxm = kxp + ((kxp >= 32) ? 192 : 0);
        float2 te[4], to[4];
#pragma unroll
        for (int hh = 0; hh < 4; ++hh) {
            int h = h0 + hh;
            te[hh] = ct[(kxm * h) & 255];
            to[hh] = ct[((kxm + 1) * h) & 255];
        }
        u64 tex[2], tey[2], teyn[2], tox[2], toy[2], toyn[2];
#pragma unroll
        for (int p = 0; p < 2; ++p) {
            tex[p]  = packab(te[2*p].x,  te[2*p+1].x);
            tey[p]  = packab(te[2*p].y,  te[2*p+1].y);
            teyn[p] = packab(-te[2*p].y, -te[2*p+1].y);
            tox[p]  = packab(to[2*p].x,  to[2*p+1].x);
            toy[p]  = packab(to[2*p].y,  to[2*p+1].y);
            toyn[p] = packab(-to[2*p].y, -to[2*p+1].y);
        }
        float4 eA = *(const float4*)&sOF[kxp * 32 + ky0];
        float4 eB = *(const float4*)&sOF[kxp * 32 + ky0 + 2];
        float4 oA = *(const float4*)&sOF[(kxp + 1) * 32 + ky0];
        float4 oB = *(const float4*)&sOF[(kxp + 1) * 32 + ky0 + 2];
        float2 ove[4] = { {eA.x, eA.y}, {eA.z, eA.w}, {eB.x, eB.y}, {eB.z, eB.w} };
        float2 ovo[4] = { {oA.x, oA.y}, {oA.z, oA.w}, {oB.x, oB.y}, {oB.z, oB.w} };
#pragma unroll
        for (int j = 0; j < 4; ++j) {
            u64 evx = pack2(ove[j].x), evy = pack2(ove[j].y);
            u64 ovx = pack2(ovo[j].x), ovy = pack2(ovo[j].y);
#pragma unroll
            for (int p = 0; p < 2; ++p) {
                Re[0][p][j] = fma2(evx, tex[p],  Re[0][p][j]);
                Re[0][p][j] = fma2(evy, teyn[p], Re[0][p][j]);
                Im[0][p][j] = fma2(evx, tey[p],  Im[0][p][j]);
                Im[0][p][j] = fma2(evy, tex[p],  Im[0][p][j]);
                Re[1][p][j] = fma2(ovx, tox[p],  Re[1][p][j]);
                Re[1][p][j] = fma2(ovy, toyn[p], Re[1][p][j]);
                Im[1][p][j] = fma2(ovx, toy[p],  Im[1][p][j]);
                Im[1][p][j] = fma2(ovy, tox[p],  Im[1][p][j]);
            }
        }
    }

    float2 ae[4][4], ao[4][4];
#pragma unroll
    for (int p = 0; p < 2; ++p)
#pragma unroll
        for (int j = 0; j < 4; ++j) {
            upk2(Re[0][p][j], ae[2*p][j].x, ae[2*p+1][j].x);
            upk2(Im[0][p][j], ae[2*p][j].y, ae[2*p+1][j].y);
            upk2(Re[1][p][j], ao[2*p][j].x, ao[2*p+1][j].x);
            upk2(Im[1][p][j], ao[2*p][j].y, ao[2*p+1][j].y);
        }
#pragma unroll
    for (int j = 0; j < 4; ++j) {
        float2* out = g_Y1 + (size_t)bc * 8192 + (ky0 + j) * 256 + h0;
#pragma unroll
        for (int hh = 0; hh < 4; hh += 2) {
            *(float4*)&out[hh] = make_float4(
                ae[hh][j].x + ao[hh][j].x,     ae[hh][j].y + ao[hh][j].y,
                ae[hh+1][j].x + ao[hh+1][j].x, ae[hh+1][j].y + ao[hh+1][j].y);
            *(float4*)&out[hh + 128] = make_float4(
                ae[hh][j].x - ao[hh][j].x,     ae[hh][j].y - ao[hh][j].y,
                ae[hh+1][j].x - ao[hh+1][j].x, ae[hh+1][j].y - ao[hh+1][j].y);
        }
    }
}

// ---- inverse rfft along W, radix-2; h-tiled (1x g_Y1 traffic), packed FFMA2 ----
__global__ void __launch_bounds__(512) k_invW() {
    extern __shared__ char smraw[];
    float2* sY2 = (float2*)smraw;               // [ky 32][hl 64] = 16KB
    float*  sWc = (float*)(smraw + 16384);      // [30..0 -> ky-1][w 128]
    float*  sWn = sWc + 31 * 128;
    __shared__ float rbuf[32];
    int tid = threadIdx.x;
    int bc = blockIdx.x >> 2, ht = blockIdx.x & 3;
    int hbase = ht * 64;

    for (int i = tid; i < 1024; i += 512) {
        int ky = i >> 5, hl2 = (i & 31) * 2;
        ((float4*)sY2)[i] = *(const float4*)(g_Y1 + (size_t)bc * 8192 + ky * 256 + hbase + hl2);
    }
    const float inv = 1.0f / 65536.0f;
    for (int i = tid; i < 31 * 128; i += 512) {
        int kyq = (i >> 7) + 1;
        int w  = i & 127;
        int idx = (kyq * w) & 255;
        sWc[i] = 2.0f * inv * g_cos[idx];
        sWn[i] = -2.0f * inv * g_sin[idx];
    }
    __syncthreads();

    int hg = tid >> 4;            // 0..31 -> 2 h each
    int wg = tid & 15;            // 0..15 -> 8 base w each
    int h0l = hg * 2;
    int w0 = wg * 8;

    u64 se2[2][4], so2[2][4];
    float dc[2];
#pragma unroll
    for (int hh = 0; hh < 2; ++hh) {
        dc[hh] = inv * sY2[h0l + hh].x;    // ky=0 row
#pragma unroll
        for (int wp = 0; wp < 4; ++wp) { se2[hh][wp] = 0ull; so2[hh][wp] = 0ull; }
    }

    for (int ky = 1; ky < 31; ky += 2) {
        {   // odd ky -> so
            float4 avv = *(const float4*)&sY2[ky * 64 + h0l];
            float2 av[2] = { {avv.x, avv.y}, {avv.z, avv.w} };
            ulonglong2 cA = *(const ulonglong2*)&sWc[(ky - 1) * 128 + w0];
            ulonglong2 cB = *(const ulonglong2*)&sWc[(ky - 1) * 128 + w0 + 4];
            ulonglong2 nA = *(const ulonglong2*)&sWn[(ky - 1) * 128 + w0];
            ulonglong2 nB = *(const ulonglong2*)&sWn[(ky - 1) * 128 + w0 + 4];
            u64 c2[4] = { cA.x, cA.y, cB.x, cB.y };
            u64 n2[4] = { nA.x, nA.y, nB.x, nB.y };
#pragma unroll
            for (int hh = 0; hh < 2; ++hh) {
                u64 axp = pack2(av[hh].x), ayp = pack2(av[hh].y);
#pragma unroll
                for (int wp = 0; wp < 4; ++wp) {
                    so2[hh][wp] = fma2(axp, c2[wp], so2[hh][wp]);
                    so2[hh][wp] = fma2(ayp, n2[wp], so2[hh][wp]);
                }
            }
        }
        {   // even ky+1 -> se
            float4 avv = *(const float4*)&sY2[(ky + 1) * 64 + h0l];
            float2 av[2] = { {avv.x, avv.y}, {avv.z, avv.w} };
            ulonglong2 cA = *(const ulonglong2*)&sWc[ky * 128 + w0];
            ulonglong2 cB = *(const ulonglong2*)&sWc[ky * 128 + w0 + 4];
            ulonglong2 nA = *(const ulonglong2*)&sWn[ky * 128 + w0];
            ulonglong2 nB = *(const ulonglong2*)&sWn[ky * 128 + w0 + 4];
            u64 c2[4] = { cA.x, cA.y, cB.x, cB.y };
            u64 n2[4] = { nA.x, nA.y, nB.x, nB.y };
#pragma unroll
            for (int hh = 0; hh < 2; ++hh) {
                u64 axp = pack2(av[hh].x), ayp = pack2(av[hh].y);
#pragma unroll
                for (int wp = 0; wp < 4; ++wp) {
                    se2[hh][wp] = fma2(axp, c2[wp], se2[hh][wp]);
                    se2[hh][wp] = fma2(ayp, n2[wp], se2[hh][wp]);
                }
            }
        }
    }
    {   // ky = 31 (odd) -> so
        float4 avv = *(const float4*)&sY2[31 * 64 + h0l];
        float2 av[2] = { {avv.x, avv.y}, {avv.z, avv.w} };
        ulonglong2 cA = *(const ulonglong2*)&sWc[30 * 128 + w0];
        ulonglong2 cB = *(const ulonglong2*)&sWc[30 * 128 + w0 + 4];
        ulonglong2 nA = *(const ulonglong2*)&sWn[30 * 128 + w0];
        ulonglong2 nB = *(const ulonglong2*)&sWn[30 * 128 + w0 + 4];
        u64 c2[4] = { cA.x, cA.y, cB.x, cB.y };
        u64 n2[4] = { nA.x, nA.y, nB.x, nB.y };
#pragma unroll
        for (int hh = 0; hh < 2; ++hh) {
            u64 axp = pack2(av[hh].x), ayp = pack2(av[hh].y);
#pragma unroll
            for (int wp = 0; wp < 4; ++wp) {
                so2[hh][wp] = fma2(axp, c2[wp], so2[hh][wp]);
                so2[hh][wp] = fma2(ayp, n2[wp], so2[hh][wp]);
            }
        }
    }

    float s = 0.0f, s2 = 0.0f;
#pragma unroll
    for (int hh = 0; hh < 2; ++hh) {
        float se[8], so[8];
#pragma unroll
        for (int wp = 0; wp < 4; ++wp) {
            upk2(se2[hh][wp], se[2 * wp], se[2 * wp + 1]);
            upk2(so2[hh][wp], so[2 * wp], so[2 * wp + 1]);
        }
        float lo[8], hi[8];
#pragma unroll
        for (int ww = 0; ww < 8; ++ww) {
            lo[ww] = dc[hh] + se[ww] + so[ww];
            hi[ww] = dc[hh] + se[ww] - so[ww];
            s += lo[ww] + hi[ww];
            s2 += lo[ww] * lo[ww] + hi[ww] * hi[ww];
        }
        size_t base = (size_t)bc * 65536 + (size_t)(hbase + h0l + hh) * 256 + w0;
        *(float4*)&g_y[base]       = make_float4(lo[0], lo[1], lo[2], lo[3]);
        *(float4*)&g_y[base + 4]   = make_float4(lo[4], lo[5], lo[6], lo[7]);
        *(float4*)&g_y[base + 128] = make_float4(hi[0], hi[1], hi[2], hi[3]);
        *(float4*)&g_y[base + 132] = make_float4(hi[4], hi[5], hi[6], hi[7]);
    }

    for (int off = 16; off > 0; off >>= 1) {
        s  += __shfl_down_sync(0xffffffffu, s,  off);
        s2 += __shfl_down_sync(0xffffffffu, s2, off);
    }
    int lane = tid & 31, wid = tid >> 5;
    if (lane == 0) { rbuf[wid] = s; rbuf[wid + 16] = s2; }
    __syncthreads();
    if (tid == 0) {
        float S = 0.0f, S2 = 0.0f;
        for (int i = 0; i < 16; ++i) { S += rbuf[i]; S2 += rbuf[i + 16]; }
        g_p1[blockIdx.x * 2] = S;
        g_p1[blockIdx.x * 2 + 1] = S2;
    }
}

__global__ void k_red1() {
    __shared__ float rbuf[16];
    int b = blockIdx.x, tid = threadIdx.x;
    float s  = g_p1[(b * 256 + tid) * 2];
    float s2 = g_p1[(b * 256 + tid) * 2 + 1];
    for (int off = 16; off > 0; off >>= 1) {
        s  += __shfl_down_sync(0xffffffffu, s,  off);
        s2 += __shfl_down_sync(0xffffffffu, s2, off);
    }
    int lane = tid & 31, wid = tid >> 5;
    if (lane == 0) { rbuf[wid] = s; rbuf[wid + 8] = s2; }
    __syncthreads();
    if (tid == 0) {
        float S = 0.0f, S2 = 0.0f;
        for (int i = 0; i < 8; ++i) { S += rbuf[i]; S2 += rbuf[i + 8]; }
        float mean = S * (1.0f / 4194304.0f);
        float var  = S2 * (1.0f / 4194304.0f) - mean * mean;
        g_s1[b * 2] = mean;
        g_s1[b * 2 + 1] = rsqrtf(var + 1e-5f);
    }
}

// ---- GN1 apply + residual + gelu + MLP (FFMA2, natural weight pairs) ----
__global__ void __launch_bounds__(256) k_mlp(const float* __restrict__ x,
                      const float* __restrict__ nw, const float* __restrict__ nb,
                      const float* __restrict__ w1, const float* __restrict__ b1,
                      const float* __restrict__ w2, const float* __restrict__ b2) {
    extern __shared__ char smraw[];
    float* sy2  = (float*)smraw;        // [c][w]  64*128
    float* sh   = sy2 + 8192;           // [m][w]  32*128
    float* sw1  = sh + 4096;            // [c][m]  64*32
    float* sw2  = sw1 + 2048;           // [m][c]  32*64
    float* sb1  = sw2 + 2048;           // 32
    float* sb2v = sb1 + 32;             // 64
    float* snw  = sb2v + 64;            // 64
    float* snb  = snw + 64;             // 64
    __shared__ float rbuf[16];

    int tid = threadIdx.x;
    int b = blockIdx.x >> 8, h = blockIdx.x & 255;

    for (int i = tid; i < 2048; i += 256) {
        int c = i >> 5, m = i & 31;
        sw1[i] = w1[m * 64 + c];
        int m2 = i >> 6, c2 = i & 63;
        sw2[i] = w2[c2 * 32 + m2];
    }
    if (tid < 64) {
        sb2v[tid] = b2[tid];
        snw[tid] = nw[tid];
        snb[tid] = nb[tid];
        if (tid < 32) sb1[tid] = b1[tid];
    }
    float mean1 = g_s1[b * 2], rstd1 = g_s1[b * 2 + 1];
    __syncthreads();

    int m0 = (tid >> 5) * 4;
    int c0 = (tid >> 5) * 8;
    int wl = (tid & 31) * 4;

    float s = 0.0f, s2 = 0.0f;
    for (int half = 0; half < 2; ++half) {
        int wbase = half * 128;

        for (int i = tid; i < 2048; i += 256) {
            int c = i >> 5, w4 = (i & 31) * 4;
            size_t gid = (size_t)(b * 64 + c) * 65536 + (size_t)h * 256 + wbase + w4;
            float4 yv = *(const float4*)&g_y[gid];
            float4 xv = *(const float4*)&x[gid];
            float a = snw[c] * rstd1, bb = snb[c] - mean1 * rstd1 * snw[c];
            float4 o;
            o.x = gelu_f(yv.x * a + bb + xv.x);
            o.y = gelu_f(yv.y * a + bb + xv.y);
            o.z = gelu_f(yv.z * a + bb + xv.z);
            o.w = gelu_f(yv.w * a + bb + xv.w);
            *(float4*)&sy2[c * 128 + w4] = o;
        }
        __syncthreads();

        {   // layer 1
            u64 acc[2][4];
#pragma unroll
            for (int p = 0; p < 2; ++p)
#pragma unroll
                for (int ww = 0; ww < 4; ++ww) acc[p][ww] = 0ull;
            for (int c = 0; c < 64; ++c) {
                ulonglong2 wp = *(const ulonglong2*)&sw1[c * 32 + m0];
                float4 yv = *(const float4*)&sy2[c * 128 + wl];
                u64 y0 = pack2(yv.x), y1 = pack2(yv.y),
                    y2 = pack2(yv.z), y3 = pack2(yv.w);
                acc[0][0] = fma2(wp.x, y0, acc[0][0]);
                acc[0][1] = fma2(wp.x, y1, acc[0][1]);
                acc[0][2] = fma2(wp.x, y2, acc[0][2]);
                acc[0][3] = fma2(wp.x, y3, acc[0][3]);
                acc[1][0] = fma2(wp.y, y0, acc[1][0]);
                acc[1][1] = fma2(wp.y, y1, acc[1][1]);
                acc[1][2] = fma2(wp.y, y2, acc[1][2]);
                acc[1][3] = fma2(wp.y, y3, acc[1][3]);
            }
#pragma unroll
            for (int p = 0; p < 2; ++p) {
                int mA = m0 + 2 * p, mB = mA + 1;
                float bA = sb1[mA], bB = sb1[mB];
#pragma unroll
                for (int ww = 0; ww < 4; ++ww) {
                    float lo, hi;
                    upk2(acc[p][ww], lo, hi);
                    sh[mA * 128 + wl + ww] = gelu_f(lo + bA);
                    sh[mB * 128 + wl + ww] = gelu_f(hi + bB);
                }
            }
        }
        __syncthreads();

        {   // layer 2
            u64 acc2[4][4];
#pragma unroll
            for (int p = 0; p < 4; ++p)
#pragma unroll
                for (int ww = 0; ww < 4; ++ww) acc2[p][ww] = 0ull;
            for (int m = 0; m < 32; ++m) {
                ulonglong2 wA = *(const ulonglong2*)&sw2[m * 64 + c0];
                ulonglong2 wB = *(const ulonglong2*)&sw2[m * 64 + c0 + 4];
                float4 hv = *(const float4*)&sh[m * 128 + wl];
                u64 h0p = pack2(hv.x), h1p = pack2(hv.y),
                    h2p = pack2(hv.z), h3p = pack2(hv.w);
                acc2[0][0] = fma2(wA.x, h0p, acc2[0][0]);
                acc2[0][1] = fma2(wA.x, h1p, acc2[0][1]);
                acc2[0][2] = fma2(wA.x, h2p, acc2[0][2]);
                acc2[0][3] = fma2(wA.x, h3p, acc2[0][3]);
                acc2[1][0] = fma2(wA.y, h0p, acc2[1][0]);
                acc2[1][1] = fma2(wA.y, h1p, acc2[1][1]);
                acc2[1][2] = fma2(wA.y, h2p, acc2[1][2]);
                acc2[1][3] = fma2(wA.y, h3p, acc2[1][3]);
                acc2[2][0] = fma2(wB.x, h0p, acc2[2][0]);
                acc2[2][1] = fma2(wB.x, h1p, acc2[2][1]);
                acc2[2][2] = fma2(wB.x, h2p, acc2[2][2]);
                acc2[2][3] = fma2(wB.x, h3p, acc2[2][3]);
                acc2[3][0] = fma2(wB.y, h0p, acc2[3][0]);
                acc2[3][1] = fma2(wB.y, h1p, acc2[3][1]);
                acc2[3][2] = fma2(wB.y, h2p, acc2[3][2]);
                acc2[3][3] = fma2(wB.y, h3p, acc2[3][3]);
            }
#pragma unroll
            for (int p = 0; p < 4; ++p) {
                int cA = c0 + 2 * p, cB = cA + 1;
                float bA = sb2v[cA], bB = sb2v[cB];
                float oA[4], oB[4];
#pragma unroll
                for (int ww = 0; ww < 4; ++ww) {
                    float lo, hi;
                    upk2(acc2[p][ww], lo, hi);
                    oA[ww] = lo + bA;
                    oB[ww] = hi + bB;
                    s += oA[ww] + oB[ww];
                    s2 += oA[ww] * oA[ww] + oB[ww] * oB[ww];
                }
                size_t gA = (size_t)(b * 64 + cA) * 65536 + (size_t)h * 256 + wbase + wl;
                size_t gB = (size_t)(b * 64 + cB) * 65536 + (size_t)h * 256 + wbase + wl;
                *(float4*)&g_z[gA] = make_float4(oA[0], oA[1], oA[2], oA[3]);
                *(float4*)&g_z[gB] = make_float4(oB[0], oB[1], oB[2], oB[3]);
            }
        }
        __syncthreads();
    }

    for (int off = 16; off > 0; off >>= 1) {
        s  += __shfl_down_sync(0xffffffffu, s,  off);
        s2 += __shfl_down_sync(0xffffffffu, s2, off);
    }
    int lane = tid & 31, widx = tid >> 5;
    if (lane == 0) { rbuf[widx] = s; rbuf[widx + 8] = s2; }
    __syncthreads();
    if (tid == 0) {
        float S = 0.0f, S2 = 0.0f;
        for (int i = 0; i < 8; ++i) { S += rbuf[i]; S2 += rbuf[i + 8]; }
        g_p2[blockIdx.x * 2] = S;
        g_p2[blockIdx.x * 2 + 1] = S2;
    }
}

__global__ void k_red2() {
    __shared__ float rbuf[16];
    int b = blockIdx.x, tid = threadIdx.x;
    float s  = g_p2[(b * 256 + tid) * 2];
    float s2 = g_p2[(b * 256 + tid) * 2 + 1];
    for (int off = 16; off > 0; off >>= 1) {
        s  += __shfl_down_sync(0xffffffffu, s,  off);
        s2 += __shfl_down_sync(0xffffffffu, s2, off);
    }
    int lane = tid & 31, wid = tid >> 5;
    if (lane == 0) { rbuf[wid] = s; rbuf[wid + 8] = s2; }
    __syncthreads();
    if (tid == 0) {
        float S = 0.0f, S2 = 0.0f;
        for (int i = 0; i < 8; ++i) { S += rbuf[i]; S2 += rbuf[i + 8]; }
        float mean = S * (1.0f / 4194304.0f);
        float var  = S2 * (1.0f / 4194304.0f) - mean * mean;
        g_s2[b * 2] = mean;
        g_s2[b * 2 + 1] = rsqrtf(var + 1e-5f);
    }
}

// ---- final: FiLM GN + skip2 ----
__global__ void k_final(const float* __restrict__ x, float* __restrict__ out) {
    int gi = blockIdx.x * 256 + threadIdx.x;
#pragma unroll
    for (int u = 0; u < 4; ++u) {
        size_t i4 = (size_t)gi + (size_t)u * 2097152;
        size_t e = i4 * 4;
        int b = (int)(e >> 22);
        int c = (int)((e >> 16) & 63);
        float mean = g_s2[b * 2], rstd = g_s2[b * 2 + 1];
        float ga = g_gb[(b * 64 + c) * 2], be = g_gb[(b * 64 + c) * 2 + 1];
        float4 zv = ((const float4*)g_z)[i4];
        float4 xv = ((const float4*)x)[i4];
        float4 ov;
        ov.x = ga * (zv.x - mean) * rstd + be + gelu_f(xv.x);
        ov.y = ga * (zv.y - mean) * rstd + be + gelu_f(xv.y);
        ov.z = ga * (zv.z - mean) * rstd + be + gelu_f(xv.z);
        ov.w = ga * (zv.w - mean) * rstd + be + gelu_f(xv.w);
        ((float4*)out)[i4] = ov;
    }
}

extern "C" void kernel_launch(void* const* d_in, const int* in_sizes, int n_in,
                              void* d_out, int out_size) {
    const float* x       = (const float*)d_in[0];
    const float* t       = (const float*)d_in[1];
    const float* w1r     = (const float*)d_in[2];
    const float* w1i     = (const float*)d_in[3];
    const float* w2r     = (const float*)d_in[4];
    const float* w2i     = (const float*)d_in[5];
    const float* norm1_w = (const float*)d_in[6];
    const float* norm1_b = (const float*)d_in[7];
    const float* mlp_w1  = (const float*)d_in[8];
    const float* mlp_b1  = (const float*)d_in[9];
    const float* mlp_w2  = (const float*)d_in[10];
    const float* mlp_b2  = (const float*)d_in[11];
    const float* gamma_w = (const float*)d_in[12];
    const float* gamma_b = (const float*)d_in[13];
    const float* beta_w  = (const float*)d_in[14];
    const float* beta_b  = (const float*)d_in[15];
    float* out = (float*)d_out;

    cudaFuncSetAttribute(k_fwdW, cudaFuncAttributeMaxDynamicSharedMemorySize, 65536);
    cudaFuncSetAttribute(k_fwdH, cudaFuncAttributeMaxDynamicSharedMemorySize, 32800);
    cudaFuncSetAttribute(k_mix,  cudaFuncAttributeMaxDynamicSharedMemorySize, 65536);
    cudaFuncSetAttribute(k_invW, cudaFuncAttributeMaxDynamicSharedMemorySize, 48128);
    cudaFuncSetAttribute(k_mlp,  cudaFuncAttributeMaxDynamicSharedMemorySize, 66432);

    k_tab<<<65, 256>>>();
    k_film<<<PB, PC>>>(t, gamma_w, gamma_b, beta_w, beta_b);
    k_fwdW<<<NROWS / 64, 256, 65536>>>(x);
    k_fwdH<<<PB * PC * 2, 256, 32800>>>();
    k_mix<<<256, 512, 65536>>>(w1r, w1i, w2r, w2i);
    k_invH<<<PB * PC, 256>>>();
    k_invW<<<PB * PC * 4, 512, 48128>>>();
    k_red1<<<PB, 256>>>();
    k_mlp<<<PB * PH, 256, 66432>>>(x, norm1_w, norm1_b,
                                   mlp_w1, mlp_b1, mlp_w2, mlp_b2);
    k_red2<<<PB, 256>>>();
    k_final<<<8192, 256>>>(x, out);
}

// round 17
// speedup vs baseline: 1.1259x; 1.1259x over previous
#include <cuda_runtime.h>
#include <math.h>

#define PB 8
#define PC 64
#define PH 256
#define PW 256
#define PKX 64
#define PKY 32
#define NROWS (PB*PC*PH)

typedef unsigned long long u64;

// ---- scratch (device globals; no runtime allocation) ----
__device__ __align__(16) float  g_T[256*64];
__device__ __align__(16) float  g_cos[256];
__device__ __align__(16) float  g_sin[256];
__device__ __align__(16) float2 g_ct[256];            // (cos, sin) pairs
__device__ __align__(16) float2 g_E[128*64];          // fwdH twiddles E[h][kxp]
__device__ __align__(16) float2 g_X1[PB*PC*PH*PKY];   // after fwd-W  [b,c,h,ky]
__device__ __align__(16) float2 g_XF[PB*PC*PKX*PKY];  // after fwd-H  [b,c,kx',ky]
__device__ __align__(16) float2 g_OF[PB*PC*PKX*PKY];  // after mix
__device__ __align__(16) float2 g_Y1[PB*PC*PKY*PH];   // after inv-H  [b,c,ky,h]
__device__ __align__(16) float  g_y[PB*PC*PH*PW];     // spectral conv out
__device__ __align__(16) float  g_z[PB*PC*PH*PW];     // MLP out
__device__ __align__(16) float  g_p1[PB*PC*4*2];
__device__ __align__(16) float  g_p2[PB*PH*2];
__device__ __align__(16) float  g_s1[PB*2];
__device__ __align__(16) float  g_s2[PB*2];
__device__ __align__(16) float  g_gb[PB*PC*2];

__device__ __forceinline__ float gelu_f(float v) {
    return 0.5f * v * (1.0f + erff(v * 0.7071067811865476f));
}

// ---- packed f32x2 helpers (bit-identical fp32 FMA, 2 per issue slot) ----
__device__ __forceinline__ u64 fma2(u64 a, u64 b, u64 c) {
    u64 d;
    asm("fma.rn.f32x2 %0, %1, %2, %3;" : "=l"(d) : "l"(a), "l"(b), "l"(c));
    return d;
}
__device__ __forceinline__ u64 pack2(float v) {
    u64 d;
    asm("mov.b64 %0, {%1, %1};" : "=l"(d) : "f"(v));
    return d;
}
__device__ __forceinline__ u64 packab(float a, float b) {
    u64 d;
    asm("mov.b64 %0, {%1, %2};" : "=l"(d) : "f"(a), "f"(b));
    return d;
}
__device__ __forceinline__ void upk2(u64 v, float& lo, float& hi) {
    asm("mov.b64 {%0, %1}, %2;" : "=f"(lo), "=f"(hi) : "l"(v));
}

// ---- twiddle tables: fully parallel grid-stride ----
__global__ void k_tab() {
    int i = blockIdx.x * blockDim.x + threadIdx.x;
    if (i < 8192) {
        int j = i >> 5, ky = i & 31;
        int idx = (ky * j) & 255;
        double s2, c2;
        sincospi((double)idx * (2.0 / 256.0), &s2, &c2);
        g_T[j * 64 + 2 * ky]     = (float)c2;
        g_T[j * 64 + 2 * ky + 1] = (float)(-s2);
    } else if (i < 8448) {
        int j = i - 8192;
        double sd, cd;
        sincospi((double)j * (2.0 / 256.0), &sd, &cd);
        g_cos[j] = (float)cd;
        g_sin[j] = (float)sd;
        g_ct[j] = make_float2((float)cd, (float)sd);
    } else if (i < 16640) {
        int k = i - 8448;
        int h = k >> 6, kxp = k & 63;
        int kxm = kxp + ((kxp >= 32) ? 192 : 0);
        int idx = (kxm * h) & 255;
        double s2, c2;
        sincospi((double)idx * (2.0 / 256.0), &s2, &c2);
        g_E[k] = make_float2((float)c2, (float)s2);
    }
}

// ---- FiLM gamma/beta ----
__global__ void k_film(const float* __restrict__ t,
                       const float* __restrict__ gw, const float* __restrict__ gb,
                       const float* __restrict__ bw, const float* __restrict__ bb) {
    int b = blockIdx.x, o = threadIdx.x;
    float g = gb[o], be = bb[o];
    for (int c = 0; c < PC; ++c) {
        float tv = t[b * PC + c];
        g  += gw[o * PC + c] * tv;
        be += bw[o * PC + c] * tv;
    }
    g_gb[(b * PC + o) * 2]     = g;
    g_gb[(b * PC + o) * 2 + 1] = be;
}

// ---- forward DFT along W, radix-2; T via LDG, packed FFMA2 ----
__global__ void __launch_bounds__(256) k_fwdW(const float* __restrict__ x) {
    extern __shared__ char smraw[];
    float2* su = (float2*)smraw;            // [row 64][w<128] (u0,u1)  64KB
    int tid = threadIdx.x;
    size_t base = (size_t)blockIdx.x * 64 * 256;

    for (int i = tid; i < 2048; i += 256) {
        int row = i >> 5, w4 = (i & 31) * 4;
        float4 a = *(const float4*)&x[base + row * 256 + w4];
        float4 b = *(const float4*)&x[base + row * 256 + w4 + 128];
        float4* d = (float4*)&su[row * 128 + w4];
        d[0] = make_float4(a.x + b.x, a.x - b.x, a.y + b.y, a.y - b.y);
        d[1] = make_float4(a.z + b.z, a.z - b.z, a.w + b.w, a.w - b.w);
    }
    __syncthreads();

    int r0 = (tid >> 3) * 2;
    int c0 = (tid & 7) * 8;

    u64 acc[2][4];
#pragma unroll
    for (int r = 0; r < 2; ++r)
#pragma unroll
        for (int p = 0; p < 4; ++p) acc[r][p] = 0ull;

    const float2* rowA = su + r0 * 128;
    const float2* rowB = rowA + 128;
#pragma unroll 4
    for (int k = 0; k < 128; ++k) {
        float2 ua = rowA[k];
        float2 ub = rowB[k];
        ulonglong2 t01 = *(const ulonglong2*)&g_T[k * 64 + c0];
        ulonglong2 t23 = *(const ulonglong2*)&g_T[k * 64 + c0 + 4];
        u64 uax = pack2(ua.x), uay = pack2(ua.y);
        u64 ubx = pack2(ub.x), uby = pack2(ub.y);
        acc[0][0] = fma2(uax, t01.x, acc[0][0]);
        acc[0][1] = fma2(uay, t01.y, acc[0][1]);
        acc[0][2] = fma2(uax, t23.x, acc[0][2]);
        acc[0][3] = fma2(uay, t23.y, acc[0][3]);
        acc[1][0] = fma2(ubx, t01.x, acc[1][0]);
        acc[1][1] = fma2(uby, t01.y, acc[1][1]);
        acc[1][2] = fma2(ubx, t23.x, acc[1][2]);
        acc[1][3] = fma2(uby, t23.y, acc[1][3]);
    }
    float* go = (float*)g_X1 + (size_t)blockIdx.x * 64 * 64;
#pragma unroll
    for (int r = 0; r < 2; ++r) {
        float o[8];
#pragma unroll
        for (int p = 0; p < 4; ++p) upk2(acc[r][p], o[2 * p], o[2 * p + 1]);
        *(float4*)&go[(r0 + r) * 64 + c0]     = make_float4(o[0], o[1], o[2], o[3]);
        *(float4*)&go[(r0 + r) * 64 + c0 + 4] = make_float4(o[4], o[5], o[6], o[7]);
    }
}

// ---- forward DFT along H, radix-2; ky-split + E via LDG + packed FFMA2 ----
__global__ void __launch_bounds__(256) k_fwdH() {
    extern __shared__ char smraw[];
    float2* sv0 = (float2*)smraw;                    // [h<128][16] sum operand
    float2* sv1 = (float2*)(smraw + 16384 + 32);     // diff operand (skewed)
    int tid = threadIdx.x;
    int bc = blockIdx.x >> 1, kh = blockIdx.x & 1;

    const float4* src = (const float4*)(g_X1 + (size_t)bc * 8192);
    float4* d0 = (float4*)sv0;
    float4* d1 = (float4*)sv1;
    for (int i = tid; i < 1024; i += 256) {
        int h = i >> 3, j = i & 7;
        int s = h * 16 + kh * 8 + j;
        float4 a = src[s];
        float4 b = src[s + 2048];                    // h+128
        d0[i] = make_float4(a.x + b.x, a.y + b.y, a.z + b.z, a.w + b.w);
        d1[i] = make_float4(a.x - b.x, a.y - b.y, a.z - b.z, a.w - b.w);
    }
    __syncthreads();

    int kxp = tid & 63;
    int ky0 = (tid >> 6) * 4;
    const float2* sv = (kxp & 1) ? sv1 : sv0;
    const float2* E = g_E + kxp;

    u64 P[4], Q[4];
#pragma unroll
    for (int j = 0; j < 4; ++j) { P[j] = 0ull; Q[j] = 0ull; }

#pragma unroll 4
    for (int h = 0; h < 128; ++h) {
        float2 e = E[h * 64];
        u64 ex = pack2(e.x), ey = pack2(e.y);
        const float2* row = &sv[h * 16 + ky0];
        ulonglong2 vA = *(const ulonglong2*)&row[0];
        ulonglong2 vB = *(const ulonglong2*)&row[2];
        P[0] = fma2(vA.x, ex, P[0]);  Q[0] = fma2(vA.x, ey, Q[0]);
        P[1] = fma2(vA.y, ex, P[1]);  Q[1] = fma2(vA.y, ey, Q[1]);
        P[2] = fma2(vB.x, ex, P[2]);  Q[2] = fma2(vB.x, ey, Q[2]);
        P[3] = fma2(vB.y, ex, P[3]);  Q[3] = fma2(vB.y, ey, Q[3]);
    }
    float2 acc[4];
#pragma unroll
    for (int j = 0; j < 4; ++j) {
        float px, py, qx, qy;
        upk2(P[j], px, py);
        upk2(Q[j], qx, qy);
        acc[j] = make_float2(px + qy, py - qx);
    }
    int kyg = kh * 16 + ky0;
    float2* o = g_XF + ((size_t)bc * 64 + kxp) * 32 + kyg;
    *(float4*)&o[0] = make_float4(acc[0].x, acc[0].y, acc[1].x, acc[1].y);
    *(float4*)&o[2] = make_float4(acc[2].x, acc[2].y, acc[3].x, acc[3].y);
}

// ---- per-mode complex channel mixing, packed FFMA2 P/Q ----
__global__ void __launch_bounds__(512)
k_mix(const float* __restrict__ w1r, const float* __restrict__ w1i,
      const float* __restrict__ w2r, const float* __restrict__ w2i) {
    extern __shared__ char smraw[];
    float2* sXF = (float2*)smraw;   // [(b*64+i)*16 + kyl], 8192 float2 = 64KB
    int kxp   = blockIdx.x >> 2;
    int ohalf = (blockIdx.x >> 1) & 1;
    int kh    = blockIdx.x & 1;
    int tid = threadIdx.x;

    for (int i = tid; i < 8192; i += 512) {
        int b = i >> 10, rest = i & 1023, ii = rest >> 4, kk = rest & 15;
        sXF[i] = g_XF[(((size_t)b * PC + ii) * PKX + kxp) * PKY + kh * 16 + kk];
    }
    __syncthreads();

    int o   = ohalf * 32 + (tid >> 4);
    int kyl = tid & 15;
    int ky  = kh * 16 + kyl;
    const float* wr; const float* wi; int kxl;
    if (kxp < 32) { wr = w1r; wi = w1i; kxl = kxp; }
    else          { wr = w2r; wi = w2i; kxl = kxp - 32; }

    u64 P[8], Q[8];
#pragma unroll
    for (int b = 0; b < 8; ++b) { P[b] = 0ull; Q[b] = 0ull; }

    const float* wrp = wr + (size_t)o * 1024 + kxl * 32 + ky;
    const float* wip = wi + (size_t)o * 1024 + kxl * 32 + ky;
#pragma unroll 4
    for (int i = 0; i < 64; ++i) {
        u64 wr2 = pack2(wrp[(size_t)i * 65536]);
        u64 wi2 = pack2(wip[(size_t)i * 65536]);
        const u64* vp = (const u64*)&sXF[i * 16 + kyl];
#pragma unroll
        for (int b = 0; b < 8; ++b) {
            u64 v = vp[b * 1024];
            P[b] = fma2(v, wr2, P[b]);
            Q[b] = fma2(v, wi2, Q[b]);
        }
    }
#pragma unroll
    for (int b = 0; b < 8; ++b) {
        float px, py, qx, qy;
        upk2(P[b], px, py);
        upk2(Q[b], qx, qy);
        g_OF[(((size_t)b * PC + o) * PKX + kxp) * PKY + ky] =
            make_float2(px - qy, py + qx);
    }
}

// ---- inverse DFT along H, radix-2; h-pair packed FFMA2 (bit-identical) ----
__global__ void __launch_bounds__(256) k_invH() {
    __shared__ float2 sOF[2048];
    __shared__ float2 ct[256];
    int tid = threadIdx.x, bc = blockIdx.x;

    const float4* src = (const float4*)(g_OF + (size_t)bc * 2048);
    float4* dst = (float4*)sOF;
    for (int i = tid; i < 1024; i += 256) dst[i] = src[i];
    ct[tid] = g_ct[tid];
    __syncthreads();

    int h0  = (tid >> 3) * 4;     // 4 h = 2 packed pairs
    int ky0 = (tid & 7) * 4;

    u64 Re[2][2][4], Im[2][2][4];
#pragma unroll
    for (int q = 0; q < 2; ++q)
#pragma unroll
        for (int p = 0; p < 2; ++p)
#pragma unroll
            for (int j = 0; j < 4; ++j) { Re[q][p][j] = 0ull; Im[q][p][j] = 0ull; }

    for (int kxp = 0; kxp < 64; kxp += 2) {
        int kxm = kxp + ((kxp >= 32) ? 192 : 0);
        float2 te[4], to[4];
#pragma unroll
        for (int hh = 0; hh < 4; ++hh) {
            int h = h0 + hh;
            te[hh] = ct[(kxm * h) & 255];
            to[hh] = ct[((kxm + 1) * h) & 255];
        }
        u64 tex[2], tey[2], teyn[2], tox[2], toy[2], toyn[2];
#pragma unroll
        for (int p = 0; p < 2; ++p) {
            tex[p]  = packab(te[2*p].x,  te[2*p+1].x);
            tey[p]  = packab(te[2*p].y,  te[2*p+1].y);
            teyn[p] = packab(-te[2*p].y, -te[2*p+1].y);
            tox[p]  = packab(to[2*p].x,  to[2*p+1].x);
            toy[p]  = packab(to[2*p].y,  to[2*p+1].y);
            toyn[p] = packab(-to[2*p].y, -to[2*p+1].y);
        }
        float4 eA = *(const float4*)&sOF[kxp * 32 + ky0];
        float4 eB = *(const float4*)&sOF[kxp * 32 + ky0 + 2];
        float4 oA = *(const float4*)&sOF[(kxp + 1) * 32 + ky0];
        float4 oB = *(const float4*)&sOF[(kxp + 1) * 32 + ky0 + 2];
        float2 ove[4] = { {eA.x, eA.y}, {eA.z, eA.w}, {eB.x, eB.y}, {eB.z, eB.w} };
        float2 ovo[4] = { {oA.x, oA.y}, {oA.z, oA.w}, {oB.x, oB.y}, {oB.z, oB.w} };
#pragma unroll
        for (int j = 0; j < 4; ++j) {
            u64 evx = pack2(ove[j].x), evy = pack2(ove[j].y);
            u64 ovx = pack2(ovo[j].x), ovy = pack2(ovo[j].y);
#pragma unroll
            for (int p = 0; p < 2; ++p) {
                Re[0][p][j] = fma2(evx, tex[p],  Re[0][p][j]);
                Re[0][p][j] = fma2(evy, teyn[p], Re[0][p][j]);
                Im[0][p][j] = fma2(evx, tey[p],  Im[0][p][j]);
                Im[0][p][j] = fma2(evy, tex[p],  Im[0][p][j]);
                Re[1][p][j] = fma2(ovx, tox[p],  Re[1][p][j]);
                Re[1][p][j] = fma2(ovy, toyn[p], Re[1][p][j]);
                Im[1][p][j] = fma2(ovx, toy[p],  Im[1][p][j]);
                Im[1][p][j] = fma2(ovy, tox[p],  Im[1][p][j]);
            }
        }
    }

    float2 ae[4][4], ao[4][4];
#pragma unroll
    for (int p = 0; p < 2; ++p)
#pragma unroll
        for (int j = 0; j < 4; ++j) {
            upk2(Re[0][p][j], ae[2*p][j].x, ae[2*p+1][j].x);
            upk2(Im[0][p][j], ae[2*p][j].y, ae[2*p+1][j].y);
            upk2(Re[1][p][j], ao[2*p][j].x, ao[2*p+1][j].x);
            upk2(Im[1][p][j], ao[2*p][j].y, ao[2*p+1][j].y);
        }
#pragma unroll
    for (int j = 0; j < 4; ++j) {
        float2* out = g_Y1 + (size_t)bc * 8192 + (ky0 + j) * 256 + h0;
#pragma unroll
        for (int hh = 0; hh < 4; hh += 2) {
            *(float4*)&out[hh] = make_float4(
                ae[hh][j].x + ao[hh][j].x,     ae[hh][j].y + ao[hh][j].y,
                ae[hh+1][j].x + ao[hh+1][j].x, ae[hh+1][j].y + ao[hh+1][j].y);
            *(float4*)&out[hh + 128] = make_float4(
                ae[hh][j].x - ao[hh][j].x,     ae[hh][j].y - ao[hh][j].y,
                ae[hh+1][j].x - ao[hh+1][j].x, ae[hh+1][j].y - ao[hh+1][j].y);
        }
    }
}

// ---- inverse rfft along W, radix-2; w-pair packed FFMA2 SoA (bit-identical) ----
__global__ void __launch_bounds__(256) k_invW() {
    extern __shared__ char smraw[];
    float2* sY  = (float2*)smraw;               // 8192 float2 (64KB)
    float*  sWc = (float*)(smraw + 65536);      // 31*32 cos*2inv
    float*  sWn = sWc + 31 * 32;                // 31*32 (-sin)*2inv
    __shared__ float rbuf[16];
    int tid = threadIdx.x;
    int bc = blockIdx.x >> 2, wt = blockIdx.x & 3;
    int w0 = wt * 32;

    const float4* src = (const float4*)(g_Y1 + (size_t)bc * 8192);
    float4* dst = (float4*)sY;
    for (int i = tid; i < 4096; i += 256) dst[i] = src[i];

    const float inv = 1.0f / 65536.0f;
    for (int i = tid; i < 31 * 32; i += 256) {
        int ky = (i >> 5) + 1;
        int w  = w0 + (i & 31);
        int idx = (ky * w) & 255;
        sWc[i] = 2.0f * inv * g_cos[idx];
        sWn[i] = -2.0f * inv * g_sin[idx];
    }
    __syncthreads();

    int h0  = (tid >> 3) * 8;
    int wth = (tid & 7) * 4;

    u64 se2[8][2], so2[8][2];
    float dc[8];
#pragma unroll
    for (int hh = 0; hh < 8; ++hh) {
        dc[hh] = inv * sY[h0 + hh].x;
#pragma unroll
        for (int wp = 0; wp < 2; ++wp) { se2[hh][wp] = 0ull; so2[hh][wp] = 0ull; }
    }

    for (int ky = 1; ky < 31; ky += 2) {
        {   // odd ky -> so
            float2 av[8];
            const float4* ap = (const float4*)&sY[ky * 256 + h0];
#pragma unroll
            for (int u = 0; u < 4; ++u) {
                float4 t1 = ap[u];
                av[2*u] = make_float2(t1.x, t1.y);
                av[2*u+1] = make_float2(t1.z, t1.w);
            }
            ulonglong2 bc2 = *(const ulonglong2*)&sWc[(ky - 1) * 32 + wth];
            ulonglong2 bn2 = *(const ulonglong2*)&sWn[(ky - 1) * 32 + wth];
#pragma unroll
            for (int hh = 0; hh < 8; ++hh) {
                u64 axp = pack2(av[hh].x), ayp = pack2(av[hh].y);
                so2[hh][0] = fma2(axp, bc2.x, so2[hh][0]);
                so2[hh][0] = fma2(ayp, bn2.x, so2[hh][0]);
                so2[hh][1] = fma2(axp, bc2.y, so2[hh][1]);
                so2[hh][1] = fma2(ayp, bn2.y, so2[hh][1]);
            }
        }
        {   // even ky+1 -> se
            float2 av[8];
            const float4* ap = (const float4*)&sY[(ky + 1) * 256 + h0];
#pragma unroll
            for (int u = 0; u < 4; ++u) {
                float4 t1 = ap[u];
                av[2*u] = make_float2(t1.x, t1.y);
                av[2*u+1] = make_float2(t1.z, t1.w);
            }
            ulonglong2 bc2 = *(const ulonglong2*)&sWc[ky * 32 + wth];
            ulonglong2 bn2 = *(const ulonglong2*)&sWn[ky * 32 + wth];
#pragma unroll
            for (int hh = 0; hh < 8; ++hh) {
                u64 axp = pack2(av[hh].x), ayp = pack2(av[hh].y);
                se2[hh][0] = fma2(axp, bc2.x, se2[hh][0]);
                se2[hh][0] = fma2(ayp, bn2.x, se2[hh][0]);
                se2[hh][1] = fma2(axp, bc2.y, se2[hh][1]);
                se2[hh][1] = fma2(ayp, bn2.y, se2[hh][1]);
            }
        }
    }
    {   // ky = 31 (odd) -> so
        float2 av[8];
        const float4* ap = (const float4*)&sY[31 * 256 + h0];
#pragma unroll
        for (int u = 0; u < 4; ++u) {
            float4 t1 = ap[u];
            av[2*u] = make_float2(t1.x, t1.y);
            av[2*u+1] = make_float2(t1.z, t1.w);
        }
        ulonglong2 bc2 = *(const ulonglong2*)&sWc[30 * 32 + wth];
        ulonglong2 bn2 = *(const ulonglong2*)&sWn[30 * 32 + wth];
#pragma unroll
        for (int hh = 0; hh < 8; ++hh) {
            u64 axp = pack2(av[hh].x), ayp = pack2(av[hh].y);
            so2[hh][0] = fma2(axp, bc2.x, so2[hh][0]);
            so2[hh][0] = fma2(ayp, bn2.x, so2[hh][0]);
            so2[hh][1] = fma2(axp, bc2.y, so2[hh][1]);
            so2[hh][1] = fma2(ayp, bn2.y, so2[hh][1]);
        }
    }

    float s = 0.0f, s2 = 0.0f;
#pragma unroll
    for (int hh = 0; hh < 8; ++hh) {
        float se[4], so[4];
        upk2(se2[hh][0], se[0], se[1]);
        upk2(se2[hh][1], se[2], se[3]);
        upk2(so2[hh][0], so[0], so[1]);
        upk2(so2[hh][1], so[2], so[3]);
        float lo[4], hi[4];
#pragma unroll
        for (int ww = 0; ww < 4; ++ww) {
            lo[ww] = dc[hh] + se[ww] + so[ww];
            hi[ww] = dc[hh] + se[ww] - so[ww];
            s += lo[ww] + hi[ww];
            s2 += lo[ww] * lo[ww] + hi[ww] * hi[ww];
        }
        size_t base = (size_t)bc * 65536 + (size_t)(h0 + hh) * 256 + w0 + wth;
        *(float4*)&g_y[base]       = make_float4(lo[0], lo[1], lo[2], lo[3]);
        *(float4*)&g_y[base + 128] = make_float4(hi[0], hi[1], hi[2], hi[3]);
    }

    for (int off = 16; off > 0; off >>= 1) {
        s  += __shfl_down_sync(0xffffffffu, s,  off);
        s2 += __shfl_down_sync(0xffffffffu, s2, off);
    }
    int lane = tid & 31, wid = tid >> 5;
    if (lane == 0) { rbuf[wid] = s; rbuf[wid + 8] = s2; }
    __syncthreads();
    if (tid == 0) {
        float S = 0.0f, S2 = 0.0f;
        for (int i = 0; i < 8; ++i) { S += rbuf[i]; S2 += rbuf[i + 8]; }
        g_p1[blockIdx.x * 2] = S;
        g_p1[blockIdx.x * 2 + 1] = S2;
    }
}

__global__ void k_red1() {
    __shared__ float rbuf[16];
    int b = blockIdx.x, tid = threadIdx.x;
    float s  = g_p1[(b * 256 + tid) * 2];
    float s2 = g_p1[(b * 256 + tid) * 2 + 1];
    for (int off = 16; off > 0; off >>= 1) {
        s  += __shfl_down_sync(0xffffffffu, s,  off);
        s2 += __shfl_down_sync(0xffffffffu, s2, off);
    }
    int lane = tid & 31, wid = tid >> 5;
    if (lane == 0) { rbuf[wid] = s; rbuf[wid + 8] = s2; }
    __syncthreads();
    if (tid == 0) {
        float S = 0.0f, S2 = 0.0f;
        for (int i = 0; i < 8; ++i) { S += rbuf[i]; S2 += rbuf[i + 8]; }
        float mean = S * (1.0f / 4194304.0f);
        float var  = S2 * (1.0f / 4194304.0f) - mean * mean;
        g_s1[b * 2] = mean;
        g_s1[b * 2 + 1] = rsqrtf(var + 1e-5f);
    }
}

// ---- GN1 apply + residual + gelu + MLP (FFMA2, natural weight pairs) ----
__global__ void __launch_bounds__(256) k_mlp(const float* __restrict__ x,
                      const float* __restrict__ nw, const float* __restrict__ nb,
                      const float* __restrict__ w1, const float* __restrict__ b1,
                      const float* __restrict__ w2, const float* __restrict__ b2) {
    extern __shared__ char smraw[];
    float* sy2  = (float*)smraw;        // [c][w]  64*128
    float* sh   = sy2 + 8192;           // [m][w]  32*128
    float* sw1  = sh + 4096;            // [c][m]  64*32
    float* sw2  = sw1 + 2048;           // [m][c]  32*64
    float* sb1  = sw2 + 2048;           // 32
    float* sb2v = sb1 + 32;             // 64
    float* snw  = sb2v + 64;            // 64
    float* snb  = snw + 64;             // 64
    __shared__ float rbuf[16];

    int tid = threadIdx.x;
    int b = blockIdx.x >> 8, h = blockIdx.x & 255;

    for (int i = tid; i < 2048; i += 256) {
        int c = i >> 5, m = i & 31;
        sw1[i] = w1[m * 64 + c];
        int m2 = i >> 6, c2 = i & 63;
        sw2[i] = w2[c2 * 32 + m2];
    }
    if (tid < 64) {
        sb2v[tid] = b2[tid];
        snw[tid] = nw[tid];
        snb[tid] = nb[tid];
        if (tid < 32) sb1[tid] = b1[tid];
    }
    float mean1 = g_s1[b * 2], rstd1 = g_s1[b * 2 + 1];
    __syncthreads();

    int m0 = (tid >> 5) * 4;
    int c0 = (tid >> 5) * 8;
    int wl = (tid & 31) * 4;

    float s = 0.0f, s2 = 0.0f;
    for (int half = 0; half < 2; ++half) {
        int wbase = half * 128;

        for (int i = tid; i < 2048; i += 256) {
            int c = i >> 5, w4 = (i & 31) * 4;
            size_t gid = (size_t)(b * 64 + c) * 65536 + (size_t)h * 256 + wbase + w4;
            float4 yv = *(const float4*)&g_y[gid];
            float4 xv = *(const float4*)&x[gid];
            float a = snw[c] * rstd1, bb = snb[c] - mean1 * rstd1 * snw[c];
            float4 o;
            o.x = gelu_f(yv.x * a + bb + xv.x);
            o.y = gelu_f(yv.y * a + bb + xv.y);
            o.z = gelu_f(yv.z * a + bb + xv.z);
            o.w = gelu_f(yv.w * a + bb + xv.w);
            *(float4*)&sy2[c * 128 + w4] = o;
        }
        __syncthreads();

        {   // layer 1
            u64 acc[2][4];
#pragma unroll
            for (int p = 0; p < 2; ++p)
#pragma unroll
                for (int ww = 0; ww < 4; ++ww) acc[p][ww] = 0ull;
            for (int c = 0; c < 64; ++c) {
                ulonglong2 wp = *(const ulonglong2*)&sw1[c * 32 + m0];
                float4 yv = *(const float4*)&sy2[c * 128 + wl];
                u64 y0 = pack2(yv.x), y1 = pack2(yv.y),
                    y2 = pack2(yv.z), y3 = pack2(yv.w);
                acc[0][0] = fma2(wp.x, y0, acc[0][0]);
                acc[0][1] = fma2(wp.x, y1, acc[0][1]);
                acc[0][2] = fma2(wp.x, y2, acc[0][2]);
                acc[0][3] = fma2(wp.x, y3, acc[0][3]);
                acc[1][0] = fma2(wp.y, y0, acc[1][0]);
                acc[1][1] = fma2(wp.y, y1, acc[1][1]);
                acc[1][2] = fma2(wp.y, y2, acc[1][2]);
                acc[1][3] = fma2(wp.y, y3, acc[1][3]);
            }
#pragma unroll
            for (int p = 0; p < 2; ++p) {
                int mA = m0 + 2 * p, mB = mA + 1;
                float bA = sb1[mA], bB = sb1[mB];
#pragma unroll
                for (int ww = 0; ww < 4; ++ww) {
                    float lo, hi;
                    upk2(acc[p][ww], lo, hi);
                    sh[mA * 128 + wl + ww] = gelu_f(lo + bA);
                    sh[mB * 128 + wl + ww] = gelu_f(hi + bB);
                }
            }
        }
        __syncthreads();

        {   // layer 2
            u64 acc2[4][4];
#pragma unroll
            for (int p = 0; p < 4; ++p)
#pragma unroll
                for (int ww = 0; ww < 4; ++ww) acc2[p][ww] = 0ull;
            for (int m = 0; m < 32; ++m) {
                ulonglong2 wA = *(const ulonglong2*)&sw2[m * 64 + c0];
                ulonglong2 wB = *(const ulonglong2*)&sw2[m * 64 + c0 + 4];
                float4 hv = *(const float4*)&sh[m * 128 + wl];
                u64 h0p = pack2(hv.x), h1p = pack2(hv.y),
                    h2p = pack2(hv.z), h3p = pack2(hv.w);
                acc2[0][0] = fma2(wA.x, h0p, acc2[0][0]);
                acc2[0][1] = fma2(wA.x, h1p, acc2[0][1]);
                acc2[0][2] = fma2(wA.x, h2p, acc2[0][2]);
                acc2[0][3] = fma2(wA.x, h3p, acc2[0][3]);
                acc2[1][0] = fma2(wA.y, h0p, acc2[1][0]);
                acc2[1][1] = fma2(wA.y, h1p, acc2[1][1]);
                acc2[1][2] = fma2(wA.y, h2p, acc2[1][2]);
                acc2[1][3] = fma2(wA.y, h3p, acc2[1][3]);
                acc2[2][0] = fma2(wB.x, h0p, acc2[2][0]);
                acc2[2][1] = fma2(wB.x, h1p, acc2[2][1]);
                acc2[2][2] = fma2(wB.x, h2p, acc2[2][2]);
                acc2[2][3] = fma2(wB.x, h3p, acc2[2][3]);
                acc2[3][0] = fma2(wB.y, h0p, acc2[3][0]);
                acc2[3][1] = fma2(wB.y, h1p, acc2[3][1]);
                acc2[3][2] = fma2(wB.y, h2p, acc2[3][2]);
                acc2[3][3] = fma2(wB.y, h3p, acc2[3][3]);
            }
#pragma unroll
            for (int p = 0; p < 4; ++p) {
                int cA = c0 + 2 * p, cB = cA + 1;
                float bA = sb2v[cA], bB = sb2v[cB];
                float oA[4], oB[4];
#pragma unroll
                for (int ww = 0; ww < 4; ++ww) {
                    float lo, hi;
                    upk2(acc2[p][ww], lo, hi);
                    oA[ww] = lo + bA;
                    oB[ww] = hi + bB;
                    s += oA[ww] + oB[ww];
                    s2 += oA[ww] * oA[ww] + oB[ww] * oB[ww];
                }
                size_t gA = (size_t)(b * 64 + cA) * 65536 + (size_t)h * 256 + wbase + wl;
                size_t gB = (size_t)(b * 64 + cB) * 65536 + (size_t)h * 256 + wbase + wl;
                *(float4*)&g_z[gA] = make_float4(oA[0], oA[1], oA[2], oA[3]);
                *(float4*)&g_z[gB] = make_float4(oB[0], oB[1], oB[2], oB[3]);
            }
        }
        __syncthreads();
    }

    for (int off = 16; off > 0; off >>= 1) {
        s  += __shfl_down_sync(0xffffffffu, s,  off);
        s2 += __shfl_down_sync(0xffffffffu, s2, off);
    }
    int lane = tid & 31, widx = tid >> 5;
    if (lane == 0) { rbuf[widx] = s; rbuf[widx + 8] = s2; }
    __syncthreads();
    if (tid == 0) {
        float S = 0.0f, S2 = 0.0f;
        for (int i = 0; i < 8; ++i) { S += rbuf[i]; S2 += rbuf[i + 8]; }
        g_p2[blockIdx.x * 2] = S;
        g_p2[blockIdx.x * 2 + 1] = S2;
    }
}

__global__ void k_red2() {
    __shared__ float rbuf[16];
    int b = blockIdx.x, tid = threadIdx.x;
    float s  = g_p2[(b * 256 + tid) * 2];
    float s2 = g_p2[(b * 256 + tid) * 2 + 1];
    for (int off = 16; off > 0; off >>= 1) {
        s  += __shfl_down_sync(0xffffffffu, s,  off);
        s2 += __shfl_down_sync(0xffffffffu, s2, off);
    }
    int lane = tid & 31, wid = tid >> 5;
    if (lane == 0) { rbuf[wid] = s; rbuf[wid + 8] = s2; }
    __syncthreads();
    if (tid == 0) {
        float S = 0.0f, S2 = 0.0f;
        for (int i = 0; i < 8; ++i) { S += rbuf[i]; S2 += rbuf[i + 8]; }
        float mean = S * (1.0f / 4194304.0f);
        float var  = S2 * (1.0f / 4194304.0f) - mean * mean;
        g_s2[b * 2] = mean;
        g_s2[b * 2 + 1] = rsqrtf(var + 1e-5f);
    }
}

// ---- final: FiLM GN + skip2 ----
__global__ void k_final(const float* __restrict__ x, float* __restrict__ out) {
    int gi = blockIdx.x * 256 + threadIdx.x;
#pragma unroll
    for (int u = 0; u < 4; ++u) {
        size_t i4 = (size_t)gi + (size_t)u * 2097152;
        size_t e = i4 * 4;
        int b = (int)(e >> 22);
        int c = (int)((e >> 16) & 63);
        float mean = g_s2[b * 2], rstd = g_s2[b * 2 + 1];
        float ga = g_gb[(b * 64 + c) * 2], be = g_gb[(b * 64 + c) * 2 + 1];
        float4 zv = ((const float4*)g_z)[i4];
        float4 xv = ((const float4*)x)[i4];
        float4 ov;
        ov.x = ga * (zv.x - mean) * rstd + be + gelu_f(xv.x);
        ov.y = ga * (zv.y - mean) * rstd + be + gelu_f(xv.y);
        ov.z = ga * (zv.z - mean) * rstd + be + gelu_f(xv.z);
        ov.w = ga * (zv.w - mean) * rstd + be + gelu_f(xv.w);
        ((float4*)out)[i4] = ov;
    }
}

extern "C" void kernel_launch(void* const* d_in, const int* in_sizes, int n_in,
                              void* d_out, int out_size) {
    const float* x       = (const float*)d_in[0];
    const float* t       = (const float*)d_in[1];
    const float* w1r     = (const float*)d_in[2];
    const float* w1i     = (const float*)d_in[3];
    const float* w2r     = (const float*)d_in[4];
    const float* w2i     = (const float*)d_in[5];
    const float* norm1_w = (const float*)d_in[6];
    const float* norm1_b = (const float*)d_in[7];
    const float* mlp_w1  = (const float*)d_in[8];
    const float* mlp_b1  = (const float*)d_in[9];
    const float* mlp_w2  = (const float*)d_in[10];
    const float* mlp_b2  = (const float*)d_in[11];
    const float* gamma_w = (const float*)d_in[12];
    const float* gamma_b = (const float*)d_in[13];
    const float* beta_w  = (const float*)d_in[14];
    const float* beta_b  = (const float*)d_in[15];
    float* out = (float*)d_out;

    cudaFuncSetAttribute(k_fwdW, cudaFuncAttributeMaxDynamicSharedMemorySize, 65536);
    cudaFuncSetAttribute(k_fwdH, cudaFuncAttributeMaxDynamicSharedMemorySize, 32800);
    cudaFuncSetAttribute(k_mix,  cudaFuncAttributeMaxDynamicSharedMemorySize, 65536);
    cudaFuncSetAttribute(k_invW, cudaFuncAttributeMaxDynamicSharedMemorySize, 73728);
    cudaFuncSetAttribute(k_mlp,  cudaFuncAttributeMaxDynamicSharedMemorySize, 66432);

    k_tab<<<65, 256>>>();
    k_film<<<PB, PC>>>(t, gamma_w, gamma_b, beta_w, beta_b);
    k_fwdW<<<NROWS / 64, 256, 65536>>>(x);
    k_fwdH<<<PB * PC * 2, 256, 32800>>>();
    k_mix<<<256, 512, 65536>>>(w1r, w1i, w2r, w2i);
    k_invH<<<PB * PC, 256>>>();
    k_invW<<<PB * PC * 4, 256, 73728>>>();
    k_red1<<<PB, 256>>>();
    k_mlp<<<PB * PH, 256, 66432>>>(x, norm1_w, norm1_b,
                                   mlp_w1, mlp_b1, mlp_w2, mlp_b2);
    k_red2<<<PB, 256>>>();
    k_final<<<8192, 256>>>(x, out);
}